// round 15
// baseline (speedup 1.0000x reference)
#include <cuda_runtime.h>
#include <math.h>

#define H    1024
#define SRC  512
#define TGT  128
#define VOUT 32000
#define G3   3072

// ---------------- scratch (static device memory; no allocations) ----------------
__device__ float g_X   [SRC * H];
__device__ float g_GIf [SRC * G3];
__device__ float g_GIb [SRC * G3];
__device__ float g_outsf[SRC * H];
__device__ float g_outsb[SRC * H];
__device__ float g_enc  [SRC * H];
__device__ float g_encT [H * SRC];
__device__ float g_XT  [TGT * 2 * H];
__device__ float g_GId [TGT * G3];
__device__ float g_H2  [TGT * H];
__device__ float g_ATT [TGT * SRC];
__device__ float g_CTX [TGT * H];
__device__ float g_CAT [TGT * 2 * H];
__device__ float g_henc[2][2][H];      // [dir][parity][H]
__device__ float g_hdec[2][H];         // [parity][H]
__device__ unsigned g_bar_ed[2];       // per-direction encoder barrier
__device__ unsigned g_bar_d;

__device__ __forceinline__ float sigmoidf_(float x) { return 1.0f / (1.0f + expf(-x)); }

// ---------------- init: zero h state + barrier counters ----------------
__global__ void init_state() {
    int i = blockIdx.x * blockDim.x + threadIdx.x;
    if (i < 4 * H) ((float*)g_henc)[i] = 0.0f;
    if (i == 0) { g_bar_ed[0] = 0u; g_bar_ed[1] = 0u; g_bar_d = 0u; }
}

// ---------------- gathers / concats ----------------
__global__ void gather_x(const int* __restrict__ wi, const float* __restrict__ emb) {
    int i = blockIdx.x * blockDim.x + threadIdx.x;
    if (i >= SRC * H) return;
    int t = i >> 10, c = i & (H - 1);
    g_X[i] = emb[(size_t)wi[t] * H + c];
}

__global__ void build_xt(const int* __restrict__ ctxi, const int* __restrict__ tgts,
                         const float* __restrict__ rarnn_emb, const float* __restrict__ dec_emb) {
    int i = blockIdx.x * blockDim.x + threadIdx.x;
    if (i >= TGT * 2 * H) return;
    int t = i >> 11, c = i & (2 * H - 1);
    float v;
    if (c < H) {
        v = rarnn_emb[(size_t)ctxi[0] * H + c];
    } else {
        int tok = (t == 0) ? 0 : tgts[t - 1];
        v = dec_emb[(size_t)tok * H + (c - H)];
    }
    g_XT[i] = v;
}

__global__ void build_cat() {
    int i = blockIdx.x * blockDim.x + threadIdx.x;
    if (i >= TGT * 2 * H) return;
    int t = i >> 11, c = i & (2 * H - 1);
    g_CAT[i] = (c < H) ? g_H2[t * H + c] : g_CTX[t * H + (c - H)];
}

__global__ void combine_enc() {
    int i = blockIdx.x * blockDim.x + threadIdx.x;
    if (i < SRC * H) {
        int t = i >> 10, c = i & (H - 1);
        float e = g_outsf[i] + g_outsb[i];
        g_enc[i] = e;
        g_encT[c * SRC + t] = e;
    }
    if (i < H) {
        g_hdec[0][i] = g_henc[0][0][i] + g_henc[1][0][i];  // 512 steps -> final parity 0
    }
}

__global__ void copy_attn(float* __restrict__ out) {
    int i = blockIdx.x * blockDim.x + threadIdx.x;
    if (i >= (TGT - 1) * SRC) return;
    out[(size_t)TGT * VOUT + i] = g_ATT[i];
}

// ---------------- SGEMM (NT), double-buffered smem pipeline ----------------
// C[M,N] = A[M,K]*B[N,K]^T (+bias)(opt sigmoid). M,N mult of 128; K mult of 16.
template <int SIG>
__global__ void __launch_bounds__(256) sgemm_nt(const float* __restrict__ A,
                                                const float* __restrict__ B,
                                                const float* __restrict__ bias,
                                                float* __restrict__ C,
                                                int M, int N, int K) {
    __shared__ float As[2][16][132];
    __shared__ float Bs[2][16][132];
    const int bm = blockIdx.y * 128, bn = blockIdx.x * 128;
    const int tid = threadIdx.x;
    const int tx = tid & 15, ty = tid >> 4;
    const int nk = K >> 4;

    // per-thread load coords (two passes cover 512 float4 = 128 rows x 16 cols)
    int row0 = tid >> 2,            c40 = (tid & 3) * 4;
    int row1 = (tid + 256) >> 2,    c41 = ((tid + 256) & 3) * 4;

    float acc[8][8];
#pragma unroll
    for (int i = 0; i < 8; i++)
#pragma unroll
        for (int j = 0; j < 8; j++) acc[i][j] = 0.0f;

    float4 ra0, ra1, rb0, rb1;
    // prologue: load k-block 0 -> buf 0
    ra0 = *(const float4*)&A[(size_t)(bm + row0) * K + c40];
    ra1 = *(const float4*)&A[(size_t)(bm + row1) * K + c41];
    rb0 = *(const float4*)&B[(size_t)(bn + row0) * K + c40];
    rb1 = *(const float4*)&B[(size_t)(bn + row1) * K + c41];
    As[0][c40 + 0][row0] = ra0.x; As[0][c40 + 1][row0] = ra0.y;
    As[0][c40 + 2][row0] = ra0.z; As[0][c40 + 3][row0] = ra0.w;
    As[0][c41 + 0][row1] = ra1.x; As[0][c41 + 1][row1] = ra1.y;
    As[0][c41 + 2][row1] = ra1.z; As[0][c41 + 3][row1] = ra1.w;
    Bs[0][c40 + 0][row0] = rb0.x; Bs[0][c40 + 1][row0] = rb0.y;
    Bs[0][c40 + 2][row0] = rb0.z; Bs[0][c40 + 3][row0] = rb0.w;
    Bs[0][c41 + 0][row1] = rb1.x; Bs[0][c41 + 1][row1] = rb1.y;
    Bs[0][c41 + 2][row1] = rb1.z; Bs[0][c41 + 3][row1] = rb1.w;
    __syncthreads();

    for (int kb = 0; kb < nk; kb++) {
        const int cur = kb & 1;
        const int nxt = cur ^ 1;
        const bool has_next = (kb + 1) < nk;
        if (has_next) {
            int k0 = (kb + 1) << 4;
            ra0 = *(const float4*)&A[(size_t)(bm + row0) * K + k0 + c40];
            ra1 = *(const float4*)&A[(size_t)(bm + row1) * K + k0 + c41];
            rb0 = *(const float4*)&B[(size_t)(bn + row0) * K + k0 + c40];
            rb1 = *(const float4*)&B[(size_t)(bn + row1) * K + k0 + c41];
        }
#pragma unroll
        for (int k = 0; k < 16; k++) {
            float4 a0 = *(const float4*)&As[cur][k][ty * 4];
            float4 a1 = *(const float4*)&As[cur][k][ty * 4 + 64];
            float4 b0 = *(const float4*)&Bs[cur][k][tx * 4];
            float4 b1 = *(const float4*)&Bs[cur][k][tx * 4 + 64];
            float av[8] = {a0.x, a0.y, a0.z, a0.w, a1.x, a1.y, a1.z, a1.w};
            float bv[8] = {b0.x, b0.y, b0.z, b0.w, b1.x, b1.y, b1.z, b1.w};
#pragma unroll
            for (int i = 0; i < 8; i++)
#pragma unroll
                for (int j = 0; j < 8; j++) acc[i][j] += av[i] * bv[j];
        }
        if (has_next) {
            As[nxt][c40 + 0][row0] = ra0.x; As[nxt][c40 + 1][row0] = ra0.y;
            As[nxt][c40 + 2][row0] = ra0.z; As[nxt][c40 + 3][row0] = ra0.w;
            As[nxt][c41 + 0][row1] = ra1.x; As[nxt][c41 + 1][row1] = ra1.y;
            As[nxt][c41 + 2][row1] = ra1.z; As[nxt][c41 + 3][row1] = ra1.w;
            Bs[nxt][c40 + 0][row0] = rb0.x; Bs[nxt][c40 + 1][row0] = rb0.y;
            Bs[nxt][c40 + 2][row0] = rb0.z; Bs[nxt][c40 + 3][row0] = rb0.w;
            Bs[nxt][c41 + 0][row1] = rb1.x; Bs[nxt][c41 + 1][row1] = rb1.y;
            Bs[nxt][c41 + 2][row1] = rb1.z; Bs[nxt][c41 + 3][row1] = rb1.w;
            __syncthreads();
        }
    }

#pragma unroll
    for (int i = 0; i < 8; i++) {
        int m = bm + ty * 4 + (i & 3) + ((i >> 2) << 6);
#pragma unroll
        for (int jj = 0; jj < 2; jj++) {
            int n0 = bn + tx * 4 + (jj << 6);
            float4 v;
            float b0 = bias ? bias[n0 + 0] : 0.0f;
            float b1 = bias ? bias[n0 + 1] : 0.0f;
            float b2 = bias ? bias[n0 + 2] : 0.0f;
            float b3 = bias ? bias[n0 + 3] : 0.0f;
            v.x = acc[i][jj * 4 + 0] + b0;
            v.y = acc[i][jj * 4 + 1] + b1;
            v.z = acc[i][jj * 4 + 2] + b2;
            v.w = acc[i][jj * 4 + 3] + b3;
            if (SIG) {
                v.x = sigmoidf_(v.x); v.y = sigmoidf_(v.y);
                v.z = sigmoidf_(v.z); v.w = sigmoidf_(v.w);
            }
            *(float4*)&C[(size_t)m * N + n0] = v;
        }
    }
}

// ---------------- grid barrier (release fence by ALL threads pre-sync) ----------
__device__ __forceinline__ void grid_barrier(unsigned* ctr, unsigned target) {
    __threadfence();
    __syncthreads();
    if (threadIdx.x == 0) {
        atomicAdd(ctr, 1u);
        while (*(volatile unsigned*)ctr < target) { }
        __threadfence();
    }
    __syncthreads();
}

// ---------------- persistent encoder scan (both directions) ----------------
// 128 blocks x 768 threads (24 warps). Blocks 0..63 fwd, 64..127 bwd.
// Block owns 16 units; warp w computes tasks {w, w+24} of 48 (unit,gate) dots.
__global__ void __launch_bounds__(768, 1) enc_scan(const float* __restrict__ whh_f,
                                                   const float* __restrict__ whh_b,
                                                   const float* __restrict__ bhh_f,
                                                   const float* __restrict__ bhh_b) {
    extern __shared__ float smem[];
    const int b   = blockIdx.x;
    const int dir = b >> 6;
    const int u0  = (b & 63) * 16;
    const float* whh = dir ? whh_b : whh_f;
    const float* bhh = dir ? bhh_b : bhh_f;
    float* wsm  = smem;                    // [task(=unit*3+gate)][1024]
    float* bsm  = smem + 16 * 3 * 1024;    // [48] (padded 64)
    float* ghsm = bsm + 64;                // [48]

    for (int i = threadIdx.x; i < 16 * 3 * 1024; i += 768) {
        int s = i / G3, rem = i % G3, g = rem >> 10, c = rem & (H - 1);
        wsm[i] = whh[((size_t)(g * H + u0 + s)) * H + c];
    }
    if (threadIdx.x < 48) {
        int s = threadIdx.x / 3, g = threadIdx.x % 3;
        bsm[threadIdx.x] = bhh[g * H + u0 + s];
    }
    __syncthreads();

    const int lane = threadIdx.x & 31, w = threadIdx.x >> 5;  // w: 0..23
    const float* gi_base = dir ? g_GIb : g_GIf;
    float* outs = dir ? g_outsb : g_outsf;

    for (int t = 0; t < SRC; t++) {
        const int p = t & 1;
        const float4* hc = (const float4*)g_henc[dir][p];
        float4 hv[8];
#pragma unroll
        for (int j = 0; j < 8; j++) hv[j] = hc[lane + j * 32];

        float acc0 = 0.f, acc1 = 0.f;
        {
            const float4* w0 = (const float4*)(wsm + w * 1024);
            const float4* w1 = (const float4*)(wsm + (w + 24) * 1024);
#pragma unroll
            for (int j = 0; j < 8; j++) {
                float4 h4 = hv[j];
                float4 v0 = w0[lane + j * 32];
                acc0 += h4.x * v0.x + h4.y * v0.y + h4.z * v0.z + h4.w * v0.w;
                float4 v1 = w1[lane + j * 32];
                acc1 += h4.x * v1.x + h4.y * v1.y + h4.z * v1.z + h4.w * v1.w;
            }
        }
#pragma unroll
        for (int o = 16; o > 0; o >>= 1) {
            acc0 += __shfl_xor_sync(0xffffffffu, acc0, o);
            acc1 += __shfl_xor_sync(0xffffffffu, acc1, o);
        }
        if (lane == 0) { ghsm[w] = acc0; ghsm[w + 24] = acc1; }
        __syncthreads();

        if (threadIdx.x < 16) {
            int s = threadIdx.x;
            int idx = u0 + s;
            int tg  = dir ? (SRC - 1 - t) : t;
            const float* gi = gi_base + (size_t)tg * G3;
            float ghr = ghsm[s * 3 + 0] + bsm[s * 3 + 0];
            float ghz = ghsm[s * 3 + 1] + bsm[s * 3 + 1];
            float ghn = ghsm[s * 3 + 2] + bsm[s * 3 + 2];
            float r = sigmoidf_(gi[idx] + ghr);
            float z = sigmoidf_(gi[H + idx] + ghz);
            float n = tanhf(gi[2 * H + idx] + r * ghn);
            float hp = g_henc[dir][p][idx];
            float h2 = (1.0f - z) * n + z * hp;
            outs[(size_t)tg * H + idx] = h2;
            g_henc[dir][p ^ 1][idx] = h2;
        }
        grid_barrier(&g_bar_ed[dir], (unsigned)(t + 1) * 64u);
    }
}

// ---------------- persistent decoder scan ----------------
// 128 blocks x 768 threads (24 warps). Block owns 8 units; warp w = task (unit,gate).
__global__ void __launch_bounds__(768, 1) dec_scan(const float* __restrict__ whh,
                                                   const float* __restrict__ bhh) {
    extern __shared__ float smem[];
    const int b = blockIdx.x;
    const int u0 = b * 8;
    float* wsm  = smem;                    // [task(=unit*3+gate)][1024]
    float* bsm  = smem + 8 * 3 * 1024;     // [24] (padded 64)
    float* ghsm = bsm + 64;                // [24]

    for (int i = threadIdx.x; i < 8 * 3 * 1024; i += 768) {
        int s = i / G3, rem = i % G3, g = rem >> 10, c = rem & (H - 1);
        wsm[i] = whh[((size_t)(g * H + u0 + s)) * H + c];
    }
    if (threadIdx.x < 24) {
        int s = threadIdx.x / 3, g = threadIdx.x % 3;
        bsm[threadIdx.x] = bhh[g * H + u0 + s];
    }
    __syncthreads();

    const int lane = threadIdx.x & 31, w = threadIdx.x >> 5;  // w: 0..23

    for (int t = 0; t < TGT; t++) {
        const int p = t & 1;
        const float4* hc = (const float4*)g_hdec[p];
        float4 hv[8];
#pragma unroll
        for (int j = 0; j < 8; j++) hv[j] = hc[lane + j * 32];

        float acc = 0.f;
        {
            const float4* wp = (const float4*)(wsm + w * 1024);
#pragma unroll
            for (int j = 0; j < 8; j++) {
                float4 h4 = hv[j];
                float4 v = wp[lane + j * 32];
                acc += h4.x * v.x + h4.y * v.y + h4.z * v.z + h4.w * v.w;
            }
        }
#pragma unroll
        for (int o = 16; o > 0; o >>= 1)
            acc += __shfl_xor_sync(0xffffffffu, acc, o);
        if (lane == 0) ghsm[w] = acc;
        __syncthreads();

        if (threadIdx.x < 8) {
            int s = threadIdx.x;
            int idx = u0 + s;
            const float* gi = g_GId + (size_t)t * G3;
            float ghr = ghsm[s * 3 + 0] + bsm[s * 3 + 0];
            float ghz = ghsm[s * 3 + 1] + bsm[s * 3 + 1];
            float ghn = ghsm[s * 3 + 2] + bsm[s * 3 + 2];
            float r = sigmoidf_(gi[idx] + ghr);
            float z = sigmoidf_(gi[H + idx] + ghz);
            float n = tanhf(gi[2 * H + idx] + r * ghn);
            float hp = g_hdec[p][idx];
            float h2 = (1.0f - z) * n + z * hp;
            g_H2[(size_t)t * H + idx] = h2;
            g_hdec[p ^ 1][idx] = h2;
        }
        grid_barrier(&g_bar_d, (unsigned)(t + 1) * 128u);
    }
}

// ---------------- log-softmax (in place, one block per row) ----------------
__global__ void __launch_bounds__(256) log_softmax_rows(float* __restrict__ x) {
    __shared__ float red[256];
    float* row = x + (size_t)blockIdx.x * VOUT;
    int tid = threadIdx.x;

    float m = -1e30f;
    for (int i = tid; i < VOUT; i += 256) m = fmaxf(m, row[i]);
    red[tid] = m; __syncthreads();
    for (int o = 128; o > 0; o >>= 1) {
        if (tid < o) red[tid] = fmaxf(red[tid], red[tid + o]);
        __syncthreads();
    }
    float M = red[0]; __syncthreads();

    float s = 0.0f;
    for (int i = tid; i < VOUT; i += 256) s += expf(row[i] - M);
    red[tid] = s; __syncthreads();
    for (int o = 128; o > 0; o >>= 1) {
        if (tid < o) red[tid] += red[tid + o];
        __syncthreads();
    }
    float lse = M + logf(red[0]); __syncthreads();

    for (int i = tid; i < VOUT; i += 256) row[i] -= lse;
}

// ---------------- launch ----------------
extern "C" void kernel_launch(void* const* d_in, const int* in_sizes, int n_in,
                              void* d_out, int out_size) {
    const int*   ctxi   = (const int*)d_in[0];
    const int*   wi     = (const int*)d_in[1];
    const int*   tgts   = (const int*)d_in[2];
    const float* rarnn  = (const float*)d_in[3];
    const float* encemb = (const float*)d_in[4];
    const float* wih_f  = (const float*)d_in[5];
    const float* whh_f  = (const float*)d_in[6];
    const float* bih_f  = (const float*)d_in[7];
    const float* bhh_f  = (const float*)d_in[8];
    const float* wih_b  = (const float*)d_in[9];
    const float* whh_b  = (const float*)d_in[10];
    const float* bih_b  = (const float*)d_in[11];
    const float* bhh_b  = (const float*)d_in[12];
    const float* decemb = (const float*)d_in[13];
    const float* dwih   = (const float*)d_in[14];
    const float* dwhh   = (const float*)d_in[15];
    const float* dbih   = (const float*)d_in[16];
    const float* dbhh   = (const float*)d_in[17];
    const float* outw   = (const float*)d_in[18];
    const float* outb   = (const float*)d_in[19];
    float* out = (float*)d_out;

    const int ENC_SMEM = (16 * 3 * 1024 + 128) * 4;
    const int DEC_SMEM = (8 * 3 * 1024 + 128) * 4;
    cudaFuncSetAttribute(enc_scan, cudaFuncAttributeMaxDynamicSharedMemorySize, ENC_SMEM);
    cudaFuncSetAttribute(dec_scan, cudaFuncAttributeMaxDynamicSharedMemorySize, DEC_SMEM);

    float *gX, *gGIf, *gGIb, *gXT, *gGId, *gH2, *gATT, *gCTX, *gCAT, *gEnc, *gEncT;
    cudaGetSymbolAddress((void**)&gX, g_X);
    cudaGetSymbolAddress((void**)&gGIf, g_GIf);
    cudaGetSymbolAddress((void**)&gGIb, g_GIb);
    cudaGetSymbolAddress((void**)&gXT, g_XT);
    cudaGetSymbolAddress((void**)&gGId, g_GId);
    cudaGetSymbolAddress((void**)&gH2, g_H2);
    cudaGetSymbolAddress((void**)&gATT, g_ATT);
    cudaGetSymbolAddress((void**)&gCTX, g_CTX);
    cudaGetSymbolAddress((void**)&gCAT, g_CAT);
    cudaGetSymbolAddress((void**)&gEnc, g_enc);
    cudaGetSymbolAddress((void**)&gEncT, g_encT);

    init_state<<<(4 * H + 255) / 256, 256>>>();

    gather_x<<<(SRC * H + 255) / 256, 256>>>(wi, encemb);
    build_xt<<<(TGT * 2 * H + 255) / 256, 256>>>(ctxi, tgts, rarnn, decemb);

    sgemm_nt<0><<<dim3(G3 / 128, SRC / 128), 256>>>(gX, wih_f, bih_f, gGIf, SRC, G3, H);
    sgemm_nt<0><<<dim3(G3 / 128, SRC / 128), 256>>>(gX, wih_b, bih_b, gGIb, SRC, G3, H);
    sgemm_nt<0><<<dim3(G3 / 128, TGT / 128), 256>>>(gXT, dwih, dbih, gGId, TGT, G3, 2 * H);

    enc_scan<<<128, 768, ENC_SMEM>>>(whh_f, whh_b, bhh_f, bhh_b);

    combine_enc<<<(SRC * H + 255) / 256, 256>>>();

    dec_scan<<<128, 768, DEC_SMEM>>>(dwhh, dbhh);

    sgemm_nt<1><<<dim3(SRC / 128, TGT / 128), 256>>>(gH2, gEnc, nullptr, gATT, TGT, SRC, H);
    sgemm_nt<0><<<dim3(H / 128, TGT / 128), 256>>>(gATT, gEncT, nullptr, gCTX, TGT, H, SRC);

    build_cat<<<(TGT * 2 * H + 255) / 256, 256>>>();
    sgemm_nt<0><<<dim3(VOUT / 128, TGT / 128), 256>>>(gCAT, outw, outb, out, TGT, VOUT, 2 * H);

    log_softmax_rows<<<TGT, 256>>>(out);
    copy_attn<<<((TGT - 1) * SRC + 255) / 256, 256>>>(out);
}

// round 16
// speedup vs baseline: 1.1931x; 1.1931x over previous
#include <cuda_runtime.h>
#include <math.h>

#define H    1024
#define SRC  512
#define TGT  128
#define VOUT 32000
#define G3   3072

// ---------------- scratch (static device memory; no allocations) ----------------
__device__ float g_X   [SRC * H];
__device__ float g_GIf [SRC * G3];
__device__ float g_GIb [SRC * G3];
__device__ float g_outsf[SRC * H];
__device__ float g_outsb[SRC * H];
__device__ float g_enc  [SRC * H];
__device__ float g_encT [H * SRC];
__device__ float g_XT  [TGT * 2 * H];
__device__ float g_GId [TGT * G3];
__device__ float g_H2  [TGT * H];
__device__ float g_ATT [TGT * SRC];
__device__ float g_CTX [TGT * H];
__device__ float g_CAT [TGT * 2 * H];
__device__ float g_henc[2][2][H];      // [dir][parity][H]
__device__ float g_hdec[2][H];         // [parity][H]
__device__ unsigned g_bar_ed[2];       // per-direction encoder barrier
__device__ unsigned g_bar_d;

__device__ __forceinline__ float sigmoidf_(float x) { return 1.0f / (1.0f + expf(-x)); }

// ---------------- init ----------------
__global__ void init_state() {
    int i = blockIdx.x * blockDim.x + threadIdx.x;
    if (i < 4 * H) ((float*)g_henc)[i] = 0.0f;
    if (i == 0) { g_bar_ed[0] = 0u; g_bar_ed[1] = 0u; g_bar_d = 0u; }
}

// ---------------- gathers / concats ----------------
__global__ void gather_x(const int* __restrict__ wi, const float* __restrict__ emb) {
    int i = blockIdx.x * blockDim.x + threadIdx.x;
    if (i >= SRC * H) return;
    int t = i >> 10, c = i & (H - 1);
    g_X[i] = emb[(size_t)wi[t] * H + c];
}

__global__ void build_xt(const int* __restrict__ ctxi, const int* __restrict__ tgts,
                         const float* __restrict__ rarnn_emb, const float* __restrict__ dec_emb) {
    int i = blockIdx.x * blockDim.x + threadIdx.x;
    if (i >= TGT * 2 * H) return;
    int t = i >> 11, c = i & (2 * H - 1);
    float v;
    if (c < H) {
        v = rarnn_emb[(size_t)ctxi[0] * H + c];
    } else {
        int tok = (t == 0) ? 0 : tgts[t - 1];
        v = dec_emb[(size_t)tok * H + (c - H)];
    }
    g_XT[i] = v;
}

__global__ void build_cat() {
    int i = blockIdx.x * blockDim.x + threadIdx.x;
    if (i >= TGT * 2 * H) return;
    int t = i >> 11, c = i & (2 * H - 1);
    g_CAT[i] = (c < H) ? g_H2[t * H + c] : g_CTX[t * H + (c - H)];
}

__global__ void combine_enc() {
    int i = blockIdx.x * blockDim.x + threadIdx.x;
    if (i < SRC * H) {
        int t = i >> 10, c = i & (H - 1);
        float e = g_outsf[i] + g_outsb[i];
        g_enc[i] = e;
        g_encT[c * SRC + t] = e;
    }
    if (i < H) {
        g_hdec[0][i] = g_henc[0][0][i] + g_henc[1][0][i];  // 512 steps -> final parity 0
    }
}

__global__ void copy_attn(float* __restrict__ out) {
    int i = blockIdx.x * blockDim.x + threadIdx.x;
    if (i >= (TGT - 1) * SRC) return;
    out[(size_t)TGT * VOUT + i] = g_ATT[i];
}

// ---------------- SGEMM (NT), double-buffered; 2 blocks/SM ----------------
template <int SIG>
__global__ void __launch_bounds__(256, 2) sgemm_nt(const float* __restrict__ A,
                                                   const float* __restrict__ B,
                                                   const float* __restrict__ bias,
                                                   float* __restrict__ C,
                                                   int M, int N, int K) {
    __shared__ float As[2][16][132];
    __shared__ float Bs[2][16][132];
    const int bm = blockIdx.y * 128, bn = blockIdx.x * 128;
    const int tid = threadIdx.x;
    const int tx = tid & 15, ty = tid >> 4;
    const int nk = K >> 4;

    int row0 = tid >> 2,            c40 = (tid & 3) * 4;
    int row1 = (tid + 256) >> 2,    c41 = ((tid + 256) & 3) * 4;

    float acc[8][8];
#pragma unroll
    for (int i = 0; i < 8; i++)
#pragma unroll
        for (int j = 0; j < 8; j++) acc[i][j] = 0.0f;

    float4 ra0, ra1, rb0, rb1;
    ra0 = *(const float4*)&A[(size_t)(bm + row0) * K + c40];
    ra1 = *(const float4*)&A[(size_t)(bm + row1) * K + c41];
    rb0 = *(const float4*)&B[(size_t)(bn + row0) * K + c40];
    rb1 = *(const float4*)&B[(size_t)(bn + row1) * K + c41];
    As[0][c40 + 0][row0] = ra0.x; As[0][c40 + 1][row0] = ra0.y;
    As[0][c40 + 2][row0] = ra0.z; As[0][c40 + 3][row0] = ra0.w;
    As[0][c41 + 0][row1] = ra1.x; As[0][c41 + 1][row1] = ra1.y;
    As[0][c41 + 2][row1] = ra1.z; As[0][c41 + 3][row1] = ra1.w;
    Bs[0][c40 + 0][row0] = rb0.x; Bs[0][c40 + 1][row0] = rb0.y;
    Bs[0][c40 + 2][row0] = rb0.z; Bs[0][c40 + 3][row0] = rb0.w;
    Bs[0][c41 + 0][row1] = rb1.x; Bs[0][c41 + 1][row1] = rb1.y;
    Bs[0][c41 + 2][row1] = rb1.z; Bs[0][c41 + 3][row1] = rb1.w;
    __syncthreads();

    for (int kb = 0; kb < nk; kb++) {
        const int cur = kb & 1;
        const int nxt = cur ^ 1;
        const bool has_next = (kb + 1) < nk;
        if (has_next) {
            int k0 = (kb + 1) << 4;
            ra0 = *(const float4*)&A[(size_t)(bm + row0) * K + k0 + c40];
            ra1 = *(const float4*)&A[(size_t)(bm + row1) * K + k0 + c41];
            rb0 = *(const float4*)&B[(size_t)(bn + row0) * K + k0 + c40];
            rb1 = *(const float4*)&B[(size_t)(bn + row1) * K + k0 + c41];
        }
#pragma unroll
        for (int k = 0; k < 16; k++) {
            float4 a0 = *(const float4*)&As[cur][k][ty * 4];
            float4 a1 = *(const float4*)&As[cur][k][ty * 4 + 64];
            float4 b0 = *(const float4*)&Bs[cur][k][tx * 4];
            float4 b1 = *(const float4*)&Bs[cur][k][tx * 4 + 64];
            float av[8] = {a0.x, a0.y, a0.z, a0.w, a1.x, a1.y, a1.z, a1.w};
            float bv[8] = {b0.x, b0.y, b0.z, b0.w, b1.x, b1.y, b1.z, b1.w};
#pragma unroll
            for (int i = 0; i < 8; i++)
#pragma unroll
                for (int j = 0; j < 8; j++) acc[i][j] += av[i] * bv[j];
        }
        if (has_next) {
            As[nxt][c40 + 0][row0] = ra0.x; As[nxt][c40 + 1][row0] = ra0.y;
            As[nxt][c40 + 2][row0] = ra0.z; As[nxt][c40 + 3][row0] = ra0.w;
            As[nxt][c41 + 0][row1] = ra1.x; As[nxt][c41 + 1][row1] = ra1.y;
            As[nxt][c41 + 2][row1] = ra1.z; As[nxt][c41 + 3][row1] = ra1.w;
            Bs[nxt][c40 + 0][row0] = rb0.x; Bs[nxt][c40 + 1][row0] = rb0.y;
            Bs[nxt][c40 + 2][row0] = rb0.z; Bs[nxt][c40 + 3][row0] = rb0.w;
            Bs[nxt][c41 + 0][row1] = rb1.x; Bs[nxt][c41 + 1][row1] = rb1.y;
            Bs[nxt][c41 + 2][row1] = rb1.z; Bs[nxt][c41 + 3][row1] = rb1.w;
            __syncthreads();
        }
    }

#pragma unroll
    for (int i = 0; i < 8; i++) {
        int m = bm + ty * 4 + (i & 3) + ((i >> 2) << 6);
#pragma unroll
        for (int jj = 0; jj < 2; jj++) {
            int n0 = bn + tx * 4 + (jj << 6);
            float4 v;
            float b0 = bias ? bias[n0 + 0] : 0.0f;
            float b1 = bias ? bias[n0 + 1] : 0.0f;
            float b2 = bias ? bias[n0 + 2] : 0.0f;
            float b3 = bias ? bias[n0 + 3] : 0.0f;
            v.x = acc[i][jj * 4 + 0] + b0;
            v.y = acc[i][jj * 4 + 1] + b1;
            v.z = acc[i][jj * 4 + 2] + b2;
            v.w = acc[i][jj * 4 + 3] + b3;
            if (SIG) {
                v.x = sigmoidf_(v.x); v.y = sigmoidf_(v.y);
                v.z = sigmoidf_(v.z); v.w = sigmoidf_(v.w);
            }
            *(float4*)&C[(size_t)m * N + n0] = v;
        }
    }
}

// ---------------- grid barrier: release fence only by writer threads ----------
__device__ __forceinline__ void grid_barrier_w(unsigned* ctr, unsigned target, bool writer) {
    if (writer) __threadfence();   // release: writers publish h2 stores
    __syncthreads();
    if (threadIdx.x == 0) {
        atomicAdd(ctr, 1u);
        while (*(volatile unsigned*)ctr < target) { }
        __threadfence();           // acquire: CCTL.IVALL flushes SM's L1
    }
    __syncthreads();
}

// ---------------- persistent encoder scan ----------------
// 128 blocks x 512 threads (16 warps). Blocks 0..63 fwd, 64..127 bwd.
// Block owns 16 units; warp w = unit w (3 gate dots). h staged via smem.
__global__ void __launch_bounds__(512, 1) enc_scan(const float* __restrict__ whh_f,
                                                   const float* __restrict__ whh_b,
                                                   const float* __restrict__ bhh_f,
                                                   const float* __restrict__ bhh_b) {
    extern __shared__ float smem[];
    const int b   = blockIdx.x;
    const int dir = b >> 6;
    const int u0  = (b & 63) * 16;
    const float* whh = dir ? whh_b : whh_f;
    const float* bhh = dir ? bhh_b : bhh_f;
    float* wsm  = smem;                    // [task=unit*3+gate][1024]
    float* bsm  = smem + 16 * 3 * 1024;    // [48] pad 64
    float* ghsm = bsm + 64;                // [48] pad 64
    float* hsm  = ghsm + 64;               // [1024] staged h

    for (int i = threadIdx.x; i < 16 * 3 * 1024; i += 512) {
        int s = i / G3, rem = i % G3, g = rem >> 10, c = rem & (H - 1);
        wsm[i] = whh[((size_t)(g * H + u0 + s)) * H + c];
    }
    if (threadIdx.x < 48) {
        int s = threadIdx.x / 3, g = threadIdx.x % 3;
        bsm[threadIdx.x] = bhh[g * H + u0 + s];
    }
    __syncthreads();

    const int tid = threadIdx.x;
    const int lane = tid & 31, w = tid >> 5;   // w: 0..15 = unit within block
    const float* gi_base = dir ? g_GIb : g_GIf;
    float* outs = dir ? g_outsb : g_outsf;

    for (int t = 0; t < SRC; t++) {
        const int p = t & 1;
        const int tg = dir ? (SRC - 1 - t) : t;

        // stage h (L2 -> smem, once per block) + prefetch GI (independent of h)
        if (tid < 256)
            ((float4*)hsm)[tid] = ((const float4*)g_henc[dir][p])[tid];
        float gir = 0.f, giz = 0.f, gin = 0.f;
        if (tid < 16) {
            const float* gi = gi_base + (size_t)tg * G3;
            int idx = u0 + tid;
            gir = gi[idx];
            giz = gi[H + idx];
            gin = gi[2 * H + idx];
        }
        __syncthreads();

        // warp w: 3 gate dots for unit w, h from smem registers
        float4 hv[8];
#pragma unroll
        for (int j = 0; j < 8; j++) hv[j] = ((const float4*)hsm)[lane + j * 32];

        const float4* w0 = (const float4*)(wsm + (w * 3 + 0) * 1024);
        const float4* w1 = (const float4*)(wsm + (w * 3 + 1) * 1024);
        const float4* w2 = (const float4*)(wsm + (w * 3 + 2) * 1024);
        float a0 = 0.f, a1 = 0.f, a2 = 0.f;
#pragma unroll
        for (int j = 0; j < 8; j++) {
            float4 h4 = hv[j];
            float4 v0 = w0[lane + j * 32];
            a0 += h4.x * v0.x + h4.y * v0.y + h4.z * v0.z + h4.w * v0.w;
            float4 v1 = w1[lane + j * 32];
            a1 += h4.x * v1.x + h4.y * v1.y + h4.z * v1.z + h4.w * v1.w;
            float4 v2 = w2[lane + j * 32];
            a2 += h4.x * v2.x + h4.y * v2.y + h4.z * v2.z + h4.w * v2.w;
        }
#pragma unroll
        for (int o = 16; o > 0; o >>= 1) {
            a0 += __shfl_xor_sync(0xffffffffu, a0, o);
            a1 += __shfl_xor_sync(0xffffffffu, a1, o);
            a2 += __shfl_xor_sync(0xffffffffu, a2, o);
        }
        if (lane == 0) {
            ghsm[w * 3 + 0] = a0;
            ghsm[w * 3 + 1] = a1;
            ghsm[w * 3 + 2] = a2;
        }
        __syncthreads();

        bool writer = (tid < 16);
        if (writer) {
            int s = tid;
            int idx = u0 + s;
            float ghr = ghsm[s * 3 + 0] + bsm[s * 3 + 0];
            float ghz = ghsm[s * 3 + 1] + bsm[s * 3 + 1];
            float ghn = ghsm[s * 3 + 2] + bsm[s * 3 + 2];
            float r = sigmoidf_(gir + ghr);
            float z = sigmoidf_(giz + ghz);
            float n = tanhf(gin + r * ghn);
            float hp = hsm[idx];
            float h2 = (1.0f - z) * n + z * hp;
            outs[(size_t)tg * H + idx] = h2;
            g_henc[dir][p ^ 1][idx] = h2;
        }
        grid_barrier_w(&g_bar_ed[dir], (unsigned)(t + 1) * 64u, writer);
    }
}

// ---------------- persistent decoder scan ----------------
// 128 blocks x 384 threads (12 warps). Block owns 8 units; warp w = tasks {2w,2w+1}.
__global__ void __launch_bounds__(384, 1) dec_scan(const float* __restrict__ whh,
                                                   const float* __restrict__ bhh) {
    extern __shared__ float smem[];
    const int b = blockIdx.x;
    const int u0 = b * 8;
    float* wsm  = smem;                    // [task][1024]
    float* bsm  = smem + 8 * 3 * 1024;     // [24] pad 64
    float* ghsm = bsm + 64;                // [24] pad 64
    float* hsm  = ghsm + 64;               // [1024]

    for (int i = threadIdx.x; i < 8 * 3 * 1024; i += 384) {
        int s = i / G3, rem = i % G3, g = rem >> 10, c = rem & (H - 1);
        wsm[i] = whh[((size_t)(g * H + u0 + s)) * H + c];
    }
    if (threadIdx.x < 24) {
        int s = threadIdx.x / 3, g = threadIdx.x % 3;
        bsm[threadIdx.x] = bhh[g * H + u0 + s];
    }
    __syncthreads();

    const int tid = threadIdx.x;
    const int lane = tid & 31, w = tid >> 5;   // w: 0..11

    for (int t = 0; t < TGT; t++) {
        const int p = t & 1;

        if (tid < 256)
            ((float4*)hsm)[tid] = ((const float4*)g_hdec[p])[tid];
        float gir = 0.f, giz = 0.f, gin = 0.f;
        if (tid < 8) {
            const float* gi = g_GId + (size_t)t * G3;
            int idx = u0 + tid;
            gir = gi[idx];
            giz = gi[H + idx];
            gin = gi[2 * H + idx];
        }
        __syncthreads();

        float4 hv[8];
#pragma unroll
        for (int j = 0; j < 8; j++) hv[j] = ((const float4*)hsm)[lane + j * 32];

        const float4* w0 = (const float4*)(wsm + (w * 2 + 0) * 1024);
        const float4* w1 = (const float4*)(wsm + (w * 2 + 1) * 1024);
        float a0 = 0.f, a1 = 0.f;
#pragma unroll
        for (int j = 0; j < 8; j++) {
            float4 h4 = hv[j];
            float4 v0 = w0[lane + j * 32];
            a0 += h4.x * v0.x + h4.y * v0.y + h4.z * v0.z + h4.w * v0.w;
            float4 v1 = w1[lane + j * 32];
            a1 += h4.x * v1.x + h4.y * v1.y + h4.z * v1.z + h4.w * v1.w;
        }
#pragma unroll
        for (int o = 16; o > 0; o >>= 1) {
            a0 += __shfl_xor_sync(0xffffffffu, a0, o);
            a1 += __shfl_xor_sync(0xffffffffu, a1, o);
        }
        if (lane == 0) {
            ghsm[w * 2 + 0] = a0;
            ghsm[w * 2 + 1] = a1;
        }
        __syncthreads();

        bool writer = (tid < 8);
        if (writer) {
            int s = tid;
            int idx = u0 + s;
            float ghr = ghsm[s * 3 + 0] + bsm[s * 3 + 0];
            float ghz = ghsm[s * 3 + 1] + bsm[s * 3 + 1];
            float ghn = ghsm[s * 3 + 2] + bsm[s * 3 + 2];
            float r = sigmoidf_(gir + ghr);
            float z = sigmoidf_(giz + ghz);
            float n = tanhf(gin + r * ghn);
            float hp = hsm[idx];
            float h2 = (1.0f - z) * n + z * hp;
            g_H2[(size_t)t * H + idx] = h2;
            g_hdec[p ^ 1][idx] = h2;
        }
        grid_barrier_w(&g_bar_d, (unsigned)(t + 1) * 128u, writer);
    }
}

// ---------------- log-softmax (in place, one block per row) ----------------
__global__ void __launch_bounds__(256) log_softmax_rows(float* __restrict__ x) {
    __shared__ float red[256];
    float* row = x + (size_t)blockIdx.x * VOUT;
    int tid = threadIdx.x;

    float m = -1e30f;
    for (int i = tid; i < VOUT; i += 256) m = fmaxf(m, row[i]);
    red[tid] = m; __syncthreads();
    for (int o = 128; o > 0; o >>= 1) {
        if (tid < o) red[tid] = fmaxf(red[tid], red[tid + o]);
        __syncthreads();
    }
    float M = red[0]; __syncthreads();

    float s = 0.0f;
    for (int i = tid; i < VOUT; i += 256) s += expf(row[i] - M);
    red[tid] = s; __syncthreads();
    for (int o = 128; o > 0; o >>= 1) {
        if (tid < o) red[tid] += red[tid + o];
        __syncthreads();
    }
    float lse = M + logf(red[0]); __syncthreads();

    for (int i = tid; i < VOUT; i += 256) row[i] -= lse;
}

// ---------------- launch ----------------
extern "C" void kernel_launch(void* const* d_in, const int* in_sizes, int n_in,
                              void* d_out, int out_size) {
    const int*   ctxi   = (const int*)d_in[0];
    const int*   wi     = (const int*)d_in[1];
    const int*   tgts   = (const int*)d_in[2];
    const float* rarnn  = (const float*)d_in[3];
    const float* encemb = (const float*)d_in[4];
    const float* wih_f  = (const float*)d_in[5];
    const float* whh_f  = (const float*)d_in[6];
    const float* bih_f  = (const float*)d_in[7];
    const float* bhh_f  = (const float*)d_in[8];
    const float* wih_b  = (const float*)d_in[9];
    const float* whh_b  = (const float*)d_in[10];
    const float* bih_b  = (const float*)d_in[11];
    const float* bhh_b  = (const float*)d_in[12];
    const float* decemb = (const float*)d_in[13];
    const float* dwih   = (const float*)d_in[14];
    const float* dwhh   = (const float*)d_in[15];
    const float* dbih   = (const float*)d_in[16];
    const float* dbhh   = (const float*)d_in[17];
    const float* outw   = (const float*)d_in[18];
    const float* outb   = (const float*)d_in[19];
    float* out = (float*)d_out;

    const int ENC_SMEM = (16 * 3 * 1024 + 64 + 64 + 1024) * 4;  // ~196.5 KB
    const int DEC_SMEM = (8 * 3 * 1024 + 64 + 64 + 1024) * 4;   // ~100.5 KB
    cudaFuncSetAttribute(enc_scan, cudaFuncAttributeMaxDynamicSharedMemorySize, ENC_SMEM);
    cudaFuncSetAttribute(dec_scan, cudaFuncAttributeMaxDynamicSharedMemorySize, DEC_SMEM);

    float *gX, *gGIf, *gGIb, *gXT, *gGId, *gH2, *gATT, *gCTX, *gCAT, *gEnc, *gEncT;
    cudaGetSymbolAddress((void**)&gX, g_X);
    cudaGetSymbolAddress((void**)&gGIf, g_GIf);
    cudaGetSymbolAddress((void**)&gGIb, g_GIb);
    cudaGetSymbolAddress((void**)&gXT, g_XT);
    cudaGetSymbolAddress((void**)&gGId, g_GId);
    cudaGetSymbolAddress((void**)&gH2, g_H2);
    cudaGetSymbolAddress((void**)&gATT, g_ATT);
    cudaGetSymbolAddress((void**)&gCTX, g_CTX);
    cudaGetSymbolAddress((void**)&gCAT, g_CAT);
    cudaGetSymbolAddress((void**)&gEnc, g_enc);
    cudaGetSymbolAddress((void**)&gEncT, g_encT);

    init_state<<<(4 * H + 255) / 256, 256>>>();

    gather_x<<<(SRC * H + 255) / 256, 256>>>(wi, encemb);
    build_xt<<<(TGT * 2 * H + 255) / 256, 256>>>(ctxi, tgts, rarnn, decemb);

    sgemm_nt<0><<<dim3(G3 / 128, SRC / 128), 256>>>(gX, wih_f, bih_f, gGIf, SRC, G3, H);
    sgemm_nt<0><<<dim3(G3 / 128, SRC / 128), 256>>>(gX, wih_b, bih_b, gGIb, SRC, G3, H);
    sgemm_nt<0><<<dim3(G3 / 128, TGT / 128), 256>>>(gXT, dwih, dbih, gGId, TGT, G3, 2 * H);

    enc_scan<<<128, 512, ENC_SMEM>>>(whh_f, whh_b, bhh_f, bhh_b);

    combine_enc<<<(SRC * H + 255) / 256, 256>>>();

    dec_scan<<<128, 384, DEC_SMEM>>>(dwhh, dbhh);

    sgemm_nt<1><<<dim3(SRC / 128, TGT / 128), 256>>>(gH2, gEnc, nullptr, gATT, TGT, SRC, H);
    sgemm_nt<0><<<dim3(H / 128, TGT / 128), 256>>>(gATT, gEncT, nullptr, gCTX, TGT, H, SRC);

    build_cat<<<(TGT * 2 * H + 255) / 256, 256>>>();
    sgemm_nt<0><<<dim3(VOUT / 128, TGT / 128), 256>>>(gCAT, outw, outb, out, TGT, VOUT, 2 * H);

    log_softmax_rows<<<TGT, 256>>>(out);
    copy_attn<<<((TGT - 1) * SRC + 255) / 256, 256>>>(out);
}